// round 9
// baseline (speedup 1.0000x reference)
#include <cuda_runtime.h>
#include <math.h>

#define DD   1024
#define NH   16
#define HDIM 64
#define FF   2048
#define BB   8
#define SS   1027
#define SP   1056
#define EPSL 1e-5f
#define NC   32             // s-chunks for ctx

typedef unsigned long long ull;

__device__ __forceinline__ ull pack2same(float v) {
    unsigned u = __float_as_uint(v);
    return ((ull)u << 32) | u;
}

#define FMA2(d, a, b) asm("fma.rn.f32x2 %0, %1, %2, %0;" : "+l"(d) : "l"(a), "l"(b))
#define ADD2(d, a, b) asm("add.rn.f32x2 %0, %1, %2;" : "=l"(d) : "l"(a), "l"(b))

__device__ float g_scores[(size_t)BB * NH * SP];     // [b][h][s]
__device__ float g_minv[BB * NH * 2];                // (max, 1/sum)
__device__ float g_qhat[NH * DD];
__device__ float g_qb[NH];
__device__ float g_ctxp[(size_t)BB * NC * NH * DD];  // split-s partial ctx
__device__ float g_ctx[(size_t)BB * NH * DD];
__device__ float g_oattn[BB * DD];
__device__ float g_ores[BB * DD];
__device__ float g_h1[BB * DD];
__device__ float g_f[BB * FF];
__device__ float g_f2[BB * DD];

// ---------- q0 + qhat: grid (NH, 4) ------------------------------------------
__global__ void k_q0qhat(const float* __restrict__ Wqkv, const float* __restrict__ bqkv,
                         const float* __restrict__ cls) {
    int h = blockIdx.x, q = blockIdx.y;
    int t = threadIdx.x;                 // 256
    int w = t >> 5, lane = t & 31;
    __shared__ __align__(16) float clss[DD];
    __shared__ float q0s[HDIM];

    for (int i = t; i < DD / 4; i += 256)
        ((float4*)clss)[i] = ((const float4*)cls)[i];
    __syncthreads();

    const float4* c4 = (const float4*)clss;
    for (int jr = 0; jr < 8; jr++) {
        int j = w * 8 + jr;
        const float4* Wr = (const float4*)(Wqkv + (size_t)(h * HDIM + j) * DD);
        float acc = 0.f;
        for (int i = lane; i < DD / 4; i += 32) {
            float4 wv = Wr[i], cv = c4[i];
            acc += wv.x * cv.x + wv.y * cv.y + wv.z * cv.z + wv.w * cv.w;
        }
        #pragma unroll
        for (int o = 16; o; o >>= 1) acc += __shfl_xor_sync(0xffffffffu, acc, o);
        if (lane == 0) q0s[j] = acc + bqkv[h * HDIM + j];
    }
    __syncthreads();

    int d = q * 256 + t;
    float acc = 0.f;
    #pragma unroll 4
    for (int j = 0; j < HDIM; j++)
        acc += q0s[j] * Wqkv[(size_t)(DD + h * HDIM + j) * DD + d];
    g_qhat[h * DD + d] = acc;
    if (q == 0 && t == 0) {
        float s = 0.f;
        for (int j = 0; j < HDIM; j++) s += q0s[j] * bqkv[DD + h * HDIM + j];
        g_qb[h] = s;
    }
}

// ---------- scores: 1 position/warp (R5 form), grid (32, BB) -------------------
__global__ void k_scores(const float* __restrict__ x, const float* __restrict__ y,
                         const float* __restrict__ cls, const float* __restrict__ sep,
                         const float* __restrict__ px, const float* __restrict__ py,
                         const int* __restrict__ x_len, const int* __restrict__ y_len) {
    extern __shared__ __align__(16) float dsm[];
    float* qh  = dsm;                    // 16384
    float* pxs = dsm + NH * DD;          // 1024
    float* pys = pxs + DD;               // 1024
    float* qbs = pys + DD;               // 16
    int b = blockIdx.y;
    int t = threadIdx.x, w = t >> 5, lane = t & 31;

    float4* qh4 = (float4*)qh;
    for (int i = t; i < NH * DD / 4; i += 256) qh4[i] = ((const float4*)g_qhat)[i];
    if (t < 256) { ((float4*)pxs)[t] = ((const float4*)px)[t]; ((float4*)pys)[t] = ((const float4*)py)[t]; }
    if (t < NH) qbs[t] = g_qb[t];
    __syncthreads();

    int lx = x_len[b], ly = y_len[b];
    int Sb = lx + ly + 3;
    const float4* pxs4 = (const float4*)pxs;
    const float4* pys4 = (const float4*)pys;

    for (int s = blockIdx.x * 8 + w; s < Sb; s += 256) {
        float4 v[8];
        if (s == 0) {
            const float4* c4 = (const float4*)cls;
            #pragma unroll
            for (int k = 0; k < 8; k++) v[k] = __ldg(&c4[lane + 32 * k]);
        } else if (s <= lx) {
            const float4* xr = (const float4*)(x + ((size_t)b * 512 + (s - 1)) * DD);
            #pragma unroll
            for (int k = 0; k < 8; k++) {
                float4 a = __ldg(&xr[lane + 32 * k]), p = pxs4[lane + 32 * k];
                v[k].x = a.x + p.x; v[k].y = a.y + p.y; v[k].z = a.z + p.z; v[k].w = a.w + p.w;
            }
        } else if (s == lx + 1 || s == lx + ly + 2) {
            const float4* s4 = (const float4*)sep;
            #pragma unroll
            for (int k = 0; k < 8; k++) v[k] = __ldg(&s4[lane + 32 * k]);
        } else {
            const float4* yr = (const float4*)(y + ((size_t)b * 512 + (s - lx - 2)) * DD);
            #pragma unroll
            for (int k = 0; k < 8; k++) {
                float4 a = __ldg(&yr[lane + 32 * k]), p = pys4[lane + 32 * k];
                v[k].x = a.x + p.x; v[k].y = a.y + p.y; v[k].z = a.z + p.z; v[k].w = a.w + p.w;
            }
        }
        float acc[NH];
        #pragma unroll
        for (int h = 0; h < NH; h++) {
            float a = 0.f;
            const float4* q4 = qh4 + h * 256;
            #pragma unroll
            for (int k = 0; k < 8; k++) {
                float4 qv = q4[lane + 32 * k];
                a += qv.x * v[k].x + qv.y * v[k].y + qv.z * v[k].z + qv.w * v[k].w;
            }
            acc[h] = a;
        }
        #pragma unroll
        for (int h = 0; h < NH; h++) {
            #pragma unroll
            for (int o = 16; o; o >>= 1)
                acc[h] += __shfl_xor_sync(0xffffffffu, acc[h], o);
        }
        if (lane == 0) {
            #pragma unroll
            for (int h = 0; h < NH; h++)
                g_scores[((size_t)b * NH + h) * SP + s] = (acc[h] + qbs[h]) * 0.125f;
        }
    }
}

// ---------- softmax stats ----------------------------------------------------
__global__ void k_stats(const int* __restrict__ x_len, const int* __restrict__ y_len) {
    int bh = blockIdx.x;
    int b  = bh >> 4;
    int Sb = x_len[b] + y_len[b] + 3;
    int t  = threadIdx.x;                // 256
    const float* sc = g_scores + (size_t)bh * SP;
    __shared__ float sred[8];

    float m = -1e30f;
    for (int s = t; s < Sb; s += 256) m = fmaxf(m, sc[s]);
    #pragma unroll
    for (int o = 16; o; o >>= 1) m = fmaxf(m, __shfl_xor_sync(0xffffffffu, m, o));
    if ((t & 31) == 0) sred[t >> 5] = m;
    __syncthreads();
    m = sred[0];
    #pragma unroll
    for (int i = 1; i < 8; i++) m = fmaxf(m, sred[i]);

    float sum = 0.f;
    for (int s = t; s < Sb; s += 256) sum += __expf(sc[s] - m);
    #pragma unroll
    for (int o = 16; o; o >>= 1) sum += __shfl_xor_sync(0xffffffffu, sum, o);
    __syncthreads();
    if ((t & 31) == 0) sred[t >> 5] = sum;
    __syncthreads();
    if (t == 0) {
        float ss = 0.f;
        #pragma unroll
        for (int i = 0; i < 8; i++) ss += sred[i];
        g_minv[bh * 2]     = m;
        g_minv[bh * 2 + 1] = 1.f / ss;
    }
}

// ---------- ctx partials: float2/thread + f32x2, grid (NC, 2, BB), block 256 ---
// one position row = DD floats = 512 ull (8B) elements.
#define ROWU 512
__global__ void __launch_bounds__(256) k_ctx(
        const float* __restrict__ x, const float* __restrict__ y,
        const float* __restrict__ cls, const float* __restrict__ sep,
        const float* __restrict__ px, const float* __restrict__ py,
        const int* __restrict__ x_len, const int* __restrict__ y_len) {
    int c  = blockIdx.x;
    int dq = blockIdx.y;           // 0..1
    int b  = blockIdx.z;
    int t  = threadIdx.x;          // 256
    int d2 = dq * 256 + t;         // float2 index 0..511
    int lx = x_len[b], ly = y_len[b];
    int Sb = lx + ly + 3;
    int cl = (Sb + NC - 1) / NC;   // <= 33
    int s0 = c * cl, s1 = min(s0 + cl, Sb);
    int n  = s1 - s0;

    if (n <= 0) {
        #pragma unroll
        for (int h = 0; h < NH; h++)
            ((ull*)(g_ctxp + (((size_t)b * NC + c) * NH + h) * DD))[d2] = 0ull;
        return;
    }

    __shared__ ull a2[NH][36];     // packed (e,e)
    __shared__ float minv[NH * 2];
    if (t < NH * 2) minv[t] = g_minv[b * NH * 2 + t];
    __syncthreads();
    for (int i = t; i < n * NH; i += 256) {
        int h = i & 15, ss = i >> 4;
        float e = __expf(g_scores[((size_t)b * NH + h) * SP + s0 + ss] - minv[h * 2]) * minv[h * 2 + 1];
        a2[h][ss] = pack2same(e);
    }
    __syncthreads();

    ull acc[NH];
    #pragma unroll
    for (int h = 0; h < NH; h++) acc[h] = 0ull;

    // cls at s = 0
    if (s0 == 0) {
        ull cv = ((const ull*)cls)[d2];
        #pragma unroll
        for (int h = 0; h < NH; h++) FMA2(acc[h], a2[h][0], cv);
    }
    // x run: s in [1, lx]
    {
        int p0 = max(s0, 1), p1 = min(s1, lx + 1);
        if (p0 < p1) {
            ull pxv = ((const ull*)px)[d2];
            const ull* xp = (const ull*)x + ((size_t)b * 512 + (p0 - 1)) * ROWU + d2;
            int nn = p1 - p0, base = p0 - s0;
            int s = 0;
            for (; s + 2 <= nn; s += 2) {
                ull r0 = xp[(size_t)s * ROWU];
                ull r1 = xp[(size_t)(s + 1) * ROWU];
                ull v0, v1;
                ADD2(v0, r0, pxv);
                ADD2(v1, r1, pxv);
                int ss = base + s;
                #pragma unroll
                for (int h = 0; h < NH; h++) {
                    FMA2(acc[h], a2[h][ss], v0);
                    FMA2(acc[h], a2[h][ss + 1], v1);
                }
            }
            if (s < nn) {
                ull r0 = xp[(size_t)s * ROWU];
                ull v0;
                ADD2(v0, r0, pxv);
                int ss = base + s;
                #pragma unroll
                for (int h = 0; h < NH; h++) FMA2(acc[h], a2[h][ss], v0);
            }
        }
    }
    // sep1 / sep2
    {
        int sA = lx + 1, sB = lx + ly + 2;
        bool hA = (sA >= s0 && sA < s1), hB = (sB >= s0 && sB < s1);
        if (hA || hB) {
            ull sv = ((const ull*)sep)[d2];
            if (hA) {
                #pragma unroll
                for (int h = 0; h < NH; h++) FMA2(acc[h], a2[h][sA - s0], sv);
            }
            if (hB) {
                #pragma unroll
                for (int h = 0; h < NH; h++) FMA2(acc[h], a2[h][sB - s0], sv);
            }
        }
    }
    // y run: s in [lx+2, lx+ly+1]
    {
        int p0 = max(s0, lx + 2), p1 = min(s1, lx + ly + 2);
        if (p0 < p1) {
            ull pyv = ((const ull*)py)[d2];
            const ull* yp = (const ull*)y + ((size_t)b * 512 + (p0 - lx - 2)) * ROWU + d2;
            int nn = p1 - p0, base = p0 - s0;
            int s = 0;
            for (; s + 2 <= nn; s += 2) {
                ull r0 = yp[(size_t)s * ROWU];
                ull r1 = yp[(size_t)(s + 1) * ROWU];
                ull v0, v1;
                ADD2(v0, r0, pyv);
                ADD2(v1, r1, pyv);
                int ss = base + s;
                #pragma unroll
                for (int h = 0; h < NH; h++) {
                    FMA2(acc[h], a2[h][ss], v0);
                    FMA2(acc[h], a2[h][ss + 1], v1);
                }
            }
            if (s < nn) {
                ull r0 = yp[(size_t)s * ROWU];
                ull v0;
                ADD2(v0, r0, pyv);
                int ss = base + s;
                #pragma unroll
                for (int h = 0; h < NH; h++) FMA2(acc[h], a2[h][ss], v0);
            }
        }
    }
    #pragma unroll
    for (int h = 0; h < NH; h++)
        ((ull*)(g_ctxp + (((size_t)b * NC + c) * NH + h) * DD))[d2] = acc[h];
}

// ---------- reduce ctx chunks: grid (BB, 32), block 128, float4 ----------------
__global__ void k_ctxreduce() {
    int b = blockIdx.x;
    int q = blockIdx.y;            // 0..31
    int t = threadIdx.x;           // 128
    int i4 = q * 128 + t;          // float4 index over NH*DD/4 = 4096
    float4 s = {0.f, 0.f, 0.f, 0.f};
    #pragma unroll
    for (int c = 0; c < NC; c++) {
        float4 v = ((const float4*)(g_ctxp + ((size_t)b * NC + c) * (NH * DD)))[i4];
        s.x += v.x; s.y += v.y; s.z += v.z; s.w += v.w;
    }
    ((float4*)(g_ctx + (size_t)b * (NH * DD)))[i4] = s;
}

// ---------- V projection: 1 row/warp, per-head ctx -----------------------------
__global__ void k_gemvV(const float* __restrict__ Wqkv, const float* __restrict__ bqkv) {
    __shared__ __align__(16) float xs[BB * DD];
    int t = threadIdx.x;           // 256
    int w = t >> 5, lane = t & 31;
    int e = blockIdx.x * 8 + w;
    int h = (blockIdx.x * 8) >> 6;

    float4* xs4 = (float4*)xs;
    for (int i = t; i < BB * DD / 4; i += 256) {
        int b = i >> 8, j4 = i & 255;
        xs4[i] = ((const float4*)(g_ctx + ((size_t)b * NH + h) * DD))[j4];
    }
    __syncthreads();

    const float4* Wr = (const float4*)(Wqkv + (size_t)(2 * DD + e) * DD);
    float acc[BB];
    #pragma unroll
    for (int b = 0; b < BB; b++) acc[b] = 0.f;
    for (int i = lane; i < DD / 4; i += 32) {
        float4 wv = Wr[i];
        #pragma unroll
        for (int b = 0; b < BB; b++) {
            float4 x4 = xs4[b * 256 + i];
            acc[b] += wv.x * x4.x + wv.y * x4.y + wv.z * x4.z + wv.w * x4.w;
        }
    }
    #pragma unroll
    for (int b = 0; b < BB; b++) {
        #pragma unroll
        for (int o = 16; o; o >>= 1)
            acc[b] += __shfl_xor_sync(0xffffffffu, acc[b], o);
    }
    if (lane == 0) {
        float be = bqkv[2 * DD + e];
        #pragma unroll
        for (int b = 0; b < BB; b++)
            g_oattn[(size_t)b * DD + e] = acc[b] + be;
    }
}

// ---------- batch-shared GEMV, optional fused input-LN --------------------------
__global__ void k_gemv8(const float* __restrict__ W, const float* __restrict__ xin,
                        const float* __restrict__ bias, const float* __restrict__ residE,
                        const float* __restrict__ residB, float* __restrict__ out,
                        int IN, int OUT, int doRelu,
                        int doLN, const float* __restrict__ lng, const float* __restrict__ lnb,
                        float* __restrict__ h1out) {
    __shared__ __align__(16) float xs[BB * 1024];
    __shared__ __align__(16) float gs[1024], bs[1024];
    int t = threadIdx.x;           // 256
    int w = t >> 5, lane = t & 31;
    int e = blockIdx.x * 8 + w;

    float acc[BB];
    #pragma unroll
    for (int b = 0; b < BB; b++) acc[b] = 0.f;

    float4* xs4 = (float4*)xs;
    int nchunk = IN >> 10;
    for (int kc = 0; kc < nchunk; kc++) {
        for (int i = t; i < BB * 256; i += 256) {
            int b = i >> 8, j4 = i & 255;
            xs4[i] = ((const float4*)(xin + (size_t)b * IN + kc * 1024))[j4];
        }
        if (doLN) {
            if (t < 256) { ((float4*)gs)[t] = ((const float4*)lng)[t]; ((float4*)bs)[t] = ((const float4*)lnb)[t]; }
            __syncthreads();
            float* row = xs + w * 1024;
            float s = 0.f;
            #pragma unroll
            for (int j = 0; j < 32; j++) s += row[lane + 32 * j];
            #pragma unroll
            for (int o = 16; o; o >>= 1) s += __shfl_xor_sync(0xffffffffu, s, o);
            float m = s * (1.f / 1024.f);
            float v = 0.f;
            #pragma unroll
            for (int j = 0; j < 32; j++) { float dd2 = row[lane + 32 * j] - m; v += dd2 * dd2; }
            #pragma unroll
            for (int o = 16; o; o >>= 1) v += __shfl_xor_sync(0xffffffffu, v, o);
            float r = rsqrtf(v * (1.f / 1024.f) + EPSL);
            #pragma unroll
            for (int j = 0; j < 32; j++) {
                int idx = lane + 32 * j;
                row[idx] = (row[idx] - m) * r * gs[idx] + bs[idx];
            }
            __syncthreads();
            if (h1out && blockIdx.x == 0) {
                for (int i = t; i < BB * 256; i += 256)
                    ((float4*)h1out)[i] = xs4[i];
            }
        } else {
            __syncthreads();
        }
        const float4* Wr = (const float4*)(W + (size_t)e * IN + kc * 1024);
        for (int i = lane; i < 256; i += 32) {
            float4 wv = Wr[i];
            #pragma unroll
            for (int b = 0; b < BB; b++) {
                float4 x4 = xs4[b * 256 + i];
                acc[b] += wv.x * x4.x + wv.y * x4.y + wv.z * x4.z + wv.w * x4.w;
            }
        }
        __syncthreads();
    }
    #pragma unroll
    for (int b = 0; b < BB; b++) {
        #pragma unroll
        for (int o = 16; o; o >>= 1)
            acc[b] += __shfl_xor_sync(0xffffffffu, acc[b], o);
    }
    if (lane == 0) {
        float be = (bias ? bias[e] : 0.f) + (residE ? residE[e] : 0.f);
        #pragma unroll
        for (int b = 0; b < BB; b++) {
            float v = acc[b] + be;
            if (residB) v += residB[(size_t)b * OUT + e];
            if (doRelu) v = fmaxf(v, 0.f);
            out[(size_t)b * OUT + e] = v;
        }
    }
}

// ---------- LayerNorm ------------------------------------------------------------
__global__ void k_ln(const float* __restrict__ in, const float* __restrict__ gamma,
                     const float* __restrict__ beta, float* __restrict__ out) {
    int b = blockIdx.x, t = threadIdx.x;  // 256
    const float* row = in + (size_t)b * DD;
    __shared__ float sred[8];
    __shared__ float smv[2];

    float s = 0.f;
    for (int i = t; i < DD; i += 256) s += row[i];
    #pragma unroll
    for (int o = 16; o; o >>= 1) s += __shfl_xor_sync(0xffffffffu, s, o);
    if ((t & 31) == 0) sred[t >> 5] = s;
    __syncthreads();
    if (t == 0) {
        float m = 0.f;
        #pragma unroll
        for (int i = 0; i < 8; i++) m += sred[i];
        smv[0] = m * (1.f / DD);
    }
    __syncthreads();
    float m = smv[0];

    float v = 0.f;
    for (int i = t; i < DD; i += 256) { float dd2 = row[i] - m; v += dd2 * dd2; }
    #pragma unroll
    for (int o = 16; o; o >>= 1) v += __shfl_xor_sync(0xffffffffu, v, o);
    __syncthreads();
    if ((t & 31) == 0) sred[t >> 5] = v;
    __syncthreads();
    if (t == 0) {
        float vv = 0.f;
        #pragma unroll
        for (int i = 0; i < 8; i++) vv += sred[i];
        smv[1] = rsqrtf(vv * (1.f / DD) + EPSL);
    }
    __syncthreads();
    float r = smv[1];
    for (int i = t; i < DD; i += 256)
        out[(size_t)b * DD + i] = (row[i] - m) * r * gamma[i] + beta[i];
}

extern "C" void kernel_launch(void* const* d_in, const int* in_sizes, int n_in,
                              void* d_out, int out_size) {
    const float* x     = (const float*)d_in[0];
    const float* y     = (const float*)d_in[1];
    const float* cls   = (const float*)d_in[2];
    const float* sep   = (const float*)d_in[3];
    const float* px    = (const float*)d_in[4];
    const float* py    = (const float*)d_in[5];
    const float* Wqkv  = (const float*)d_in[6];
    const float* bqkv  = (const float*)d_in[7];
    const float* Wo    = (const float*)d_in[8];
    const float* bo    = (const float*)d_in[9];
    const float* W1    = (const float*)d_in[10];
    const float* b1    = (const float*)d_in[11];
    const float* W2    = (const float*)d_in[12];
    const float* b2    = (const float*)d_in[13];
    const float* ln1g  = (const float*)d_in[14];
    const float* ln1b  = (const float*)d_in[15];
    const float* ln2g  = (const float*)d_in[16];
    const float* ln2b  = (const float*)d_in[17];
    const int*   x_len = (const int*)d_in[18];
    const int*   y_len = (const int*)d_in[19];
    float* outp = (float*)d_out;

    float *p_oattn, *p_ores, *p_h1, *p_f, *p_f2;
    cudaGetSymbolAddress((void**)&p_oattn, g_oattn);
    cudaGetSymbolAddress((void**)&p_ores,  g_ores);
    cudaGetSymbolAddress((void**)&p_h1,    g_h1);
    cudaGetSymbolAddress((void**)&p_f,     g_f);
    cudaGetSymbolAddress((void**)&p_f2,    g_f2);

    const int SCORES_SMEM = (NH * DD + 2 * DD + 16) * (int)sizeof(float);  // ~74KB
    cudaFuncSetAttribute(k_scores, cudaFuncAttributeMaxDynamicSharedMemorySize, SCORES_SMEM);

    k_q0qhat<<<dim3(NH, 4), 256>>>(Wqkv, bqkv, cls);
    k_scores<<<dim3(32, BB), 256, SCORES_SMEM>>>(x, y, cls, sep, px, py, x_len, y_len);
    k_stats<<<BB * NH, 256>>>(x_len, y_len);
    k_ctx<<<dim3(NC, 2, BB), 256>>>(x, y, cls, sep, px, py, x_len, y_len);
    k_ctxreduce<<<dim3(BB, 32), 128>>>();
    k_gemvV<<<DD / 8, 256>>>(Wqkv, bqkv);
    k_gemv8<<<DD / 8, 256>>>(Wo, p_oattn, bo, cls, nullptr, p_ores, DD, DD, 0,
                             0, nullptr, nullptr, nullptr);
    k_gemv8<<<FF / 8, 256>>>(W1, p_ores, b1, nullptr, nullptr, p_f, DD, FF, 1,
                             1, ln1g, ln1b, p_h1);
    k_gemv8<<<DD / 8, 256>>>(W2, p_f, b2, nullptr, p_h1, p_f2, FF, DD, 0,
                             0, nullptr, nullptr, nullptr);
    k_ln<<<BB, 256>>>(p_f2, ln2g, ln2b, outp);
}

// round 10
// speedup vs baseline: 1.0292x; 1.0292x over previous
#include <cuda_runtime.h>
#include <math.h>

#define DD   1024
#define NH   16
#define HDIM 64
#define FF   2048
#define BB   8
#define SS   1027
#define SP   1056
#define EPSL 1e-5f
#define NC   32             // s-chunks for ctx

typedef unsigned long long ull;

__device__ __forceinline__ ull pack2same(float v) {
    unsigned u = __float_as_uint(v);
    return ((ull)u << 32) | u;
}

#define FMA2(d, a, b) asm("fma.rn.f32x2 %0, %1, %2, %0;" : "+l"(d) : "l"(a), "l"(b))
#define ADD2(d, a, b) asm("add.rn.f32x2 %0, %1, %2;" : "=l"(d) : "l"(a), "l"(b))

__device__ float g_scores[(size_t)BB * NH * SP];     // [b][h][s]
__device__ float g_minv[BB * NH * 2];                // (max, 1/sum)
__device__ float g_qhat[NH * DD];
__device__ float g_qb[NH];
__device__ float g_ctxp[(size_t)BB * NC * NH * DD];  // split-s partial ctx
__device__ float g_ctx[(size_t)BB * NH * DD];
__device__ float g_oattn[BB * DD];
__device__ float g_ores[BB * DD];
__device__ float g_h1[BB * DD];
__device__ float g_f[BB * FF];
__device__ float g_f2[BB * DD];

// ---------- q0 + qhat: grid (NH, 4) ------------------------------------------
__global__ void k_q0qhat(const float* __restrict__ Wqkv, const float* __restrict__ bqkv,
                         const float* __restrict__ cls) {
    int h = blockIdx.x, q = blockIdx.y;
    int t = threadIdx.x;                 // 256
    int w = t >> 5, lane = t & 31;
    __shared__ __align__(16) float clss[DD];
    __shared__ float q0s[HDIM];

    for (int i = t; i < DD / 4; i += 256)
        ((float4*)clss)[i] = ((const float4*)cls)[i];
    __syncthreads();

    const float4* c4 = (const float4*)clss;
    for (int jr = 0; jr < 8; jr++) {
        int j = w * 8 + jr;
        const float4* Wr = (const float4*)(Wqkv + (size_t)(h * HDIM + j) * DD);
        float acc = 0.f;
        for (int i = lane; i < DD / 4; i += 32) {
            float4 wv = Wr[i], cv = c4[i];
            acc += wv.x * cv.x + wv.y * cv.y + wv.z * cv.z + wv.w * cv.w;
        }
        #pragma unroll
        for (int o = 16; o; o >>= 1) acc += __shfl_xor_sync(0xffffffffu, acc, o);
        if (lane == 0) q0s[j] = acc + bqkv[h * HDIM + j];
    }
    __syncthreads();

    int d = q * 256 + t;
    float acc = 0.f;
    #pragma unroll 4
    for (int j = 0; j < HDIM; j++)
        acc += q0s[j] * Wqkv[(size_t)(DD + h * HDIM + j) * DD + d];
    g_qhat[h * DD + d] = acc;
    if (q == 0 && t == 0) {
        float s = 0.f;
        for (int j = 0; j < HDIM; j++) s += q0s[j] * bqkv[DD + h * HDIM + j];
        g_qb[h] = s;
    }
}

// ---------- position fetch helper (float4 regs) --------------------------------
__device__ __forceinline__ void fetch_pos(
    int s, int lx, int ly, int b, int lane,
    const float* __restrict__ x, const float* __restrict__ y,
    const float* __restrict__ cls, const float* __restrict__ sep,
    const float4* __restrict__ pxs4, const float4* __restrict__ pys4,
    float4 v[8]) {
    if (s == 0) {
        const float4* c4 = (const float4*)cls;
        #pragma unroll
        for (int k = 0; k < 8; k++) v[k] = __ldg(&c4[lane + 32 * k]);
    } else if (s <= lx) {
        const float4* xr = (const float4*)(x + ((size_t)b * 512 + (s - 1)) * DD);
        #pragma unroll
        for (int k = 0; k < 8; k++) {
            float4 a = __ldg(&xr[lane + 32 * k]), p = pxs4[lane + 32 * k];
            v[k].x = a.x + p.x; v[k].y = a.y + p.y; v[k].z = a.z + p.z; v[k].w = a.w + p.w;
        }
    } else if (s == lx + 1 || s == lx + ly + 2) {
        const float4* s4 = (const float4*)sep;
        #pragma unroll
        for (int k = 0; k < 8; k++) v[k] = __ldg(&s4[lane + 32 * k]);
    } else {
        const float4* yr = (const float4*)(y + ((size_t)b * 512 + (s - lx - 2)) * DD);
        #pragma unroll
        for (int k = 0; k < 8; k++) {
            float4 a = __ldg(&yr[lane + 32 * k]), p = pys4[lane + 32 * k];
            v[k].x = a.x + p.x; v[k].y = a.y + p.y; v[k].z = a.z + p.z; v[k].w = a.w + p.w;
        }
    }
}

// ---------- scores: 2 positions/warp, scalar dots, grid (16, BB) ---------------
__global__ void k_scores(const float* __restrict__ x, const float* __restrict__ y,
                         const float* __restrict__ cls, const float* __restrict__ sep,
                         const float* __restrict__ px, const float* __restrict__ py,
                         const int* __restrict__ x_len, const int* __restrict__ y_len) {
    extern __shared__ __align__(16) float dsm[];
    float* qh  = dsm;                    // 16384
    float* pxs = dsm + NH * DD;          // 1024
    float* pys = pxs + DD;               // 1024
    float* qbs = pys + DD;               // 16
    int b = blockIdx.y;
    int t = threadIdx.x, w = t >> 5, lane = t & 31;

    float4* qh4 = (float4*)qh;
    for (int i = t; i < NH * DD / 4; i += 256) qh4[i] = ((const float4*)g_qhat)[i];
    if (t < 256) { ((float4*)pxs)[t] = ((const float4*)px)[t]; ((float4*)pys)[t] = ((const float4*)py)[t]; }
    if (t < NH) qbs[t] = g_qb[t];
    __syncthreads();

    int lx = x_len[b], ly = y_len[b];
    int Sb = lx + ly + 3;
    const float4* pxs4 = (const float4*)pxs;
    const float4* pys4 = (const float4*)pys;

    for (int s = blockIdx.x * 16 + w * 2; s < Sb; s += 256) {
        bool two = (s + 1 < Sb);
        float4 v0[8], v1[8];
        fetch_pos(s, lx, ly, b, lane, x, y, cls, sep, pxs4, pys4, v0);
        if (two) fetch_pos(s + 1, lx, ly, b, lane, x, y, cls, sep, pxs4, pys4, v1);

        float acc0[NH], acc1[NH];
        #pragma unroll
        for (int h = 0; h < NH; h++) {
            float a0 = 0.f, a1 = 0.f;
            const float4* q4 = qh4 + h * 256;
            #pragma unroll
            for (int k = 0; k < 8; k++) {
                float4 qv = q4[lane + 32 * k];
                a0 += qv.x * v0[k].x + qv.y * v0[k].y + qv.z * v0[k].z + qv.w * v0[k].w;
                if (two)
                    a1 += qv.x * v1[k].x + qv.y * v1[k].y + qv.z * v1[k].z + qv.w * v1[k].w;
            }
            acc0[h] = a0; acc1[h] = a1;
        }
        #pragma unroll
        for (int h = 0; h < NH; h++) {
            #pragma unroll
            for (int o = 16; o; o >>= 1) {
                acc0[h] += __shfl_xor_sync(0xffffffffu, acc0[h], o);
                acc1[h] += __shfl_xor_sync(0xffffffffu, acc1[h], o);
            }
        }
        if (lane == 0) {
            #pragma unroll
            for (int h = 0; h < NH; h++) {
                float* sp = g_scores + ((size_t)b * NH + h) * SP + s;
                sp[0] = (acc0[h] + qbs[h]) * 0.125f;
                if (two) sp[1] = (acc1[h] + qbs[h]) * 0.125f;
            }
        }
    }
}

// ---------- softmax stats ----------------------------------------------------
__global__ void k_stats(const int* __restrict__ x_len, const int* __restrict__ y_len) {
    int bh = blockIdx.x;
    int b  = bh >> 4;
    int Sb = x_len[b] + y_len[b] + 3;
    int t  = threadIdx.x;                // 256
    const float* sc = g_scores + (size_t)bh * SP;
    __shared__ float sred[8];

    float m = -1e30f;
    for (int s = t; s < Sb; s += 256) m = fmaxf(m, sc[s]);
    #pragma unroll
    for (int o = 16; o; o >>= 1) m = fmaxf(m, __shfl_xor_sync(0xffffffffu, m, o));
    if ((t & 31) == 0) sred[t >> 5] = m;
    __syncthreads();
    m = sred[0];
    #pragma unroll
    for (int i = 1; i < 8; i++) m = fmaxf(m, sred[i]);

    float sum = 0.f;
    for (int s = t; s < Sb; s += 256) sum += __expf(sc[s] - m);
    #pragma unroll
    for (int o = 16; o; o >>= 1) sum += __shfl_xor_sync(0xffffffffu, sum, o);
    __syncthreads();
    if ((t & 31) == 0) sred[t >> 5] = sum;
    __syncthreads();
    if (t == 0) {
        float ss = 0.f;
        #pragma unroll
        for (int i = 0; i < 8; i++) ss += sred[i];
        g_minv[bh * 2]     = m;
        g_minv[bh * 2 + 1] = 1.f / ss;
    }
}

// ---------- ctx partials: float2/thread + f32x2, grid (NC, 2, BB), block 256 ---
#define ROWU 512
__global__ void __launch_bounds__(256) k_ctx(
        const float* __restrict__ x, const float* __restrict__ y,
        const float* __restrict__ cls, const float* __restrict__ sep,
        const float* __restrict__ px, const float* __restrict__ py,
        const int* __restrict__ x_len, const int* __restrict__ y_len) {
    int c  = blockIdx.x;
    int dq = blockIdx.y;           // 0..1
    int b  = blockIdx.z;
    int t  = threadIdx.x;          // 256
    int d2 = dq * 256 + t;         // float2 index 0..511
    int lx = x_len[b], ly = y_len[b];
    int Sb = lx + ly + 3;
    int cl = (Sb + NC - 1) / NC;   // <= 33
    int s0 = c * cl, s1 = min(s0 + cl, Sb);
    int n  = s1 - s0;

    if (n <= 0) {
        #pragma unroll
        for (int h = 0; h < NH; h++)
            ((ull*)(g_ctxp + (((size_t)b * NC + c) * NH + h) * DD))[d2] = 0ull;
        return;
    }

    __shared__ ull a2[NH][36];     // packed (e,e)
    __shared__ float minv[NH * 2];
    if (t < NH * 2) minv[t] = g_minv[b * NH * 2 + t];
    __syncthreads();
    for (int i = t; i < n * NH; i += 256) {
        int h = i & 15, ss = i >> 4;
        float e = __expf(g_scores[((size_t)b * NH + h) * SP + s0 + ss] - minv[h * 2]) * minv[h * 2 + 1];
        a2[h][ss] = pack2same(e);
    }
    __syncthreads();

    ull acc[NH];
    #pragma unroll
    for (int h = 0; h < NH; h++) acc[h] = 0ull;

    if (s0 == 0) {
        ull cv = ((const ull*)cls)[d2];
        #pragma unroll
        for (int h = 0; h < NH; h++) FMA2(acc[h], a2[h][0], cv);
    }
    {
        int p0 = max(s0, 1), p1 = min(s1, lx + 1);
        if (p0 < p1) {
            ull pxv = ((const ull*)px)[d2];
            const ull* xp = (const ull*)x + ((size_t)b * 512 + (p0 - 1)) * ROWU + d2;
            int nn = p1 - p0, base = p0 - s0;
            int s = 0;
            for (; s + 2 <= nn; s += 2) {
                ull r0 = xp[(size_t)s * ROWU];
                ull r1 = xp[(size_t)(s + 1) * ROWU];
                ull v0, v1;
                ADD2(v0, r0, pxv);
                ADD2(v1, r1, pxv);
                int ss = base + s;
                #pragma unroll
                for (int h = 0; h < NH; h++) {
                    FMA2(acc[h], a2[h][ss], v0);
                    FMA2(acc[h], a2[h][ss + 1], v1);
                }
            }
            if (s < nn) {
                ull r0 = xp[(size_t)s * ROWU];
                ull v0;
                ADD2(v0, r0, pxv);
                int ss = base + s;
                #pragma unroll
                for (int h = 0; h < NH; h++) FMA2(acc[h], a2[h][ss], v0);
            }
        }
    }
    {
        int sA = lx + 1, sB = lx + ly + 2;
        bool hA = (sA >= s0 && sA < s1), hB = (sB >= s0 && sB < s1);
        if (hA || hB) {
            ull sv = ((const ull*)sep)[d2];
            if (hA) {
                #pragma unroll
                for (int h = 0; h < NH; h++) FMA2(acc[h], a2[h][sA - s0], sv);
            }
            if (hB) {
                #pragma unroll
                for (int h = 0; h < NH; h++) FMA2(acc[h], a2[h][sB - s0], sv);
            }
        }
    }
    {
        int p0 = max(s0, lx + 2), p1 = min(s1, lx + ly + 2);
        if (p0 < p1) {
            ull pyv = ((const ull*)py)[d2];
            const ull* yp = (const ull*)y + ((size_t)b * 512 + (p0 - lx - 2)) * ROWU + d2;
            int nn = p1 - p0, base = p0 - s0;
            int s = 0;
            for (; s + 2 <= nn; s += 2) {
                ull r0 = yp[(size_t)s * ROWU];
                ull r1 = yp[(size_t)(s + 1) * ROWU];
                ull v0, v1;
                ADD2(v0, r0, pyv);
                ADD2(v1, r1, pyv);
                int ss = base + s;
                #pragma unroll
                for (int h = 0; h < NH; h++) {
                    FMA2(acc[h], a2[h][ss], v0);
                    FMA2(acc[h], a2[h][ss + 1], v1);
                }
            }
            if (s < nn) {
                ull r0 = yp[(size_t)s * ROWU];
                ull v0;
                ADD2(v0, r0, pyv);
                int ss = base + s;
                #pragma unroll
                for (int h = 0; h < NH; h++) FMA2(acc[h], a2[h][ss], v0);
            }
        }
    }
    #pragma unroll
    for (int h = 0; h < NH; h++)
        ((ull*)(g_ctxp + (((size_t)b * NC + c) * NH + h) * DD))[d2] = acc[h];
}

// ---------- reduce ctx chunks: grid (BB, 16), block 256, float4 ----------------
__global__ void k_ctxreduce() {
    int b = blockIdx.x;
    int q = blockIdx.y;            // 0..15
    int t = threadIdx.x;           // 256
    int i4 = q * 256 + t;          // float4 index over NH*DD/4 = 4096
    float4 s = {0.f, 0.f, 0.f, 0.f};
    #pragma unroll
    for (int c = 0; c < NC; c++) {
        float4 v = ((const float4*)(g_ctxp + ((size_t)b * NC + c) * (NH * DD)))[i4];
        s.x += v.x; s.y += v.y; s.z += v.z; s.w += v.w;
    }
    ((float4*)(g_ctx + (size_t)b * (NH * DD)))[i4] = s;
}

// ---------- V projection: 1 row/warp, per-head ctx -----------------------------
__global__ void k_gemvV(const float* __restrict__ Wqkv, const float* __restrict__ bqkv) {
    __shared__ __align__(16) float xs[BB * DD];
    int t = threadIdx.x;           // 256
    int w = t >> 5, lane = t & 31;
    int e = blockIdx.x * 8 + w;
    int h = (blockIdx.x * 8) >> 6;

    float4* xs4 = (float4*)xs;
    for (int i = t; i < BB * DD / 4; i += 256) {
        int b = i >> 8, j4 = i & 255;
        xs4[i] = ((const float4*)(g_ctx + ((size_t)b * NH + h) * DD))[j4];
    }
    __syncthreads();

    const float4* Wr = (const float4*)(Wqkv + (size_t)(2 * DD + e) * DD);
    float acc[BB];
    #pragma unroll
    for (int b = 0; b < BB; b++) acc[b] = 0.f;
    for (int i = lane; i < DD / 4; i += 32) {
        float4 wv = Wr[i];
        #pragma unroll
        for (int b = 0; b < BB; b++) {
            float4 x4 = xs4[b * 256 + i];
            acc[b] += wv.x * x4.x + wv.y * x4.y + wv.z * x4.z + wv.w * x4.w;
        }
    }
    #pragma unroll
    for (int b = 0; b < BB; b++) {
        #pragma unroll
        for (int o = 16; o; o >>= 1)
            acc[b] += __shfl_xor_sync(0xffffffffu, acc[b], o);
    }
    if (lane == 0) {
        float be = bqkv[2 * DD + e];
        #pragma unroll
        for (int b = 0; b < BB; b++)
            g_oattn[(size_t)b * DD + e] = acc[b] + be;
    }
}

// ---------- batch-shared GEMV, optional fused input-LN --------------------------
__global__ void k_gemv8(const float* __restrict__ W, const float* __restrict__ xin,
                        const float* __restrict__ bias, const float* __restrict__ residE,
                        const float* __restrict__ residB, float* __restrict__ out,
                        int IN, int OUT, int doRelu,
                        int doLN, const float* __restrict__ lng, const float* __restrict__ lnb,
                        float* __restrict__ h1out) {
    __shared__ __align__(16) float xs[BB * 1024];
    __shared__ __align__(16) float gs[1024], bs[1024];
    int t = threadIdx.x;           // 256
    int w = t >> 5, lane = t & 31;
    int e = blockIdx.x * 8 + w;

    float acc[BB];
    #pragma unroll
    for (int b = 0; b < BB; b++) acc[b] = 0.f;

    float4* xs4 = (float4*)xs;
    int nchunk = IN >> 10;
    for (int kc = 0; kc < nchunk; kc++) {
        for (int i = t; i < BB * 256; i += 256) {
            int b = i >> 8, j4 = i & 255;
            xs4[i] = ((const float4*)(xin + (size_t)b * IN + kc * 1024))[j4];
        }
        if (doLN) {
            if (t < 256) { ((float4*)gs)[t] = ((const float4*)lng)[t]; ((float4*)bs)[t] = ((const float4*)lnb)[t]; }
            __syncthreads();
            float* row = xs + w * 1024;
            float s = 0.f;
            #pragma unroll
            for (int j = 0; j < 32; j++) s += row[lane + 32 * j];
            #pragma unroll
            for (int o = 16; o; o >>= 1) s += __shfl_xor_sync(0xffffffffu, s, o);
            float m = s * (1.f / 1024.f);
            float v = 0.f;
            #pragma unroll
            for (int j = 0; j < 32; j++) { float dd2 = row[lane + 32 * j] - m; v += dd2 * dd2; }
            #pragma unroll
            for (int o = 16; o; o >>= 1) v += __shfl_xor_sync(0xffffffffu, v, o);
            float r = rsqrtf(v * (1.f / 1024.f) + EPSL);
            #pragma unroll
            for (int j = 0; j < 32; j++) {
                int idx = lane + 32 * j;
                row[idx] = (row[idx] - m) * r * gs[idx] + bs[idx];
            }
            __syncthreads();
            if (h1out && blockIdx.x == 0) {
                for (int i = t; i < BB * 256; i += 256)
                    ((float4*)h1out)[i] = xs4[i];
            }
        } else {
            __syncthreads();
        }
        const float4* Wr = (const float4*)(W + (size_t)e * IN + kc * 1024);
        for (int i = lane; i < 256; i += 32) {
            float4 wv = Wr[i];
            #pragma unroll
            for (int b = 0; b < BB; b++) {
                float4 x4 = xs4[b * 256 + i];
                acc[b] += wv.x * x4.x + wv.y * x4.y + wv.z * x4.z + wv.w * x4.w;
            }
        }
        __syncthreads();
    }
    #pragma unroll
    for (int b = 0; b < BB; b++) {
        #pragma unroll
        for (int o = 16; o; o >>= 1)
            acc[b] += __shfl_xor_sync(0xffffffffu, acc[b], o);
    }
    if (lane == 0) {
        float be = (bias ? bias[e] : 0.f) + (residE ? residE[e] : 0.f);
        #pragma unroll
        for (int b = 0; b < BB; b++) {
            float v = acc[b] + be;
            if (residB) v += residB[(size_t)b * OUT + e];
            if (doRelu) v = fmaxf(v, 0.f);
            out[(size_t)b * OUT + e] = v;
        }
    }
}

// ---------- LayerNorm ------------------------------------------------------------
__global__ void k_ln(const float* __restrict__ in, const float* __restrict__ gamma,
                     const float* __restrict__ beta, float* __restrict__ out) {
    int b = blockIdx.x, t = threadIdx.x;  // 256
    const float* row = in + (size_t)b * DD;
    __shared__ float sred[8];
    __shared__ float smv[2];

    float s = 0.f;
    for (int i = t; i < DD; i += 256) s += row[i];
    #pragma unroll
    for (int o = 16; o; o >>= 1) s += __shfl_xor_sync(0xffffffffu, s, o);
    if ((t & 31) == 0) sred[t >> 5] = s;
    __syncthreads();
    if (t == 0) {
        float m = 0.f;
        #pragma unroll
        for (int i = 0; i < 8; i++) m += sred[i];
        smv[0] = m * (1.f / DD);
    }
    __syncthreads();
    float m = smv[0];

    float v = 0.f;
    for (int i = t; i < DD; i += 256) { float dd2 = row[i] - m; v += dd2 * dd2; }
    #pragma unroll
    for (int o = 16; o; o >>= 1) v += __shfl_xor_sync(0xffffffffu, v, o);
    __syncthreads();
    if ((t & 31) == 0) sred[t >> 5] = v;
    __syncthreads();
    if (t == 0) {
        float vv = 0.f;
        #pragma unroll
        for (int i = 0; i < 8; i++) vv += sred[i];
        smv[1] = rsqrtf(vv * (1.f / DD) + EPSL);
    }
    __syncthreads();
    float r = smv[1];
    for (int i = t; i < DD; i += 256)
        out[(size_t)b * DD + i] = (row[i] - m) * r * gamma[i] + beta[i];
}

extern "C" void kernel_launch(void* const* d_in, const int* in_sizes, int n_in,
                              void* d_out, int out_size) {
    const float* x     = (const float*)d_in[0];
    const float* y     = (const float*)d_in[1];
    const float* cls   = (const float*)d_in[2];
    const float* sep   = (const float*)d_in[3];
    const float* px    = (const float*)d_in[4];
    const float* py    = (const float*)d_in[5];
    const float* Wqkv  = (const float*)d_in[6];
    const float* bqkv  = (const float*)d_in[7];
    const float* Wo    = (const float*)d_in[8];
    const float* bo    = (const float*)d_in[9];
    const float* W1    = (const float*)d_in[10];
    const float* b1    = (const float*)d_in[11];
    const float* W2    = (const float*)d_in[12];
    const float* b2    = (const float*)d_in[13];
    const float* ln1g  = (const float*)d_in[14];
    const float* ln1b  = (const float*)d_in[15];
    const float* ln2g  = (const float*)d_in[16];
    const float* ln2b  = (const float*)d_in[17];
    const int*   x_len = (const int*)d_in[18];
    const int*   y_len = (const int*)d_in[19];
    float* outp = (float*)d_out;

    float *p_oattn, *p_ores, *p_h1, *p_f, *p_f2;
    cudaGetSymbolAddress((void**)&p_oattn, g_oattn);
    cudaGetSymbolAddress((void**)&p_ores,  g_ores);
    cudaGetSymbolAddress((void**)&p_h1,    g_h1);
    cudaGetSymbolAddress((void**)&p_f,     g_f);
    cudaGetSymbolAddress((void**)&p_f2,    g_f2);

    const int SCORES_SMEM = (NH * DD + 2 * DD + 16) * (int)sizeof(float);  // ~74KB
    cudaFuncSetAttribute(k_scores, cudaFuncAttributeMaxDynamicSharedMemorySize, SCORES_SMEM);

    k_q0qhat<<<dim3(NH, 4), 256>>>(Wqkv, bqkv, cls);
    k_scores<<<dim3(16, BB), 256, SCORES_SMEM>>>(x, y, cls, sep, px, py, x_len, y_len);
    k_stats<<<BB * NH, 256>>>(x_len, y_len);
    k_ctx<<<dim3(NC, 2, BB), 256>>>(x, y, cls, sep, px, py, x_len, y_len);
    k_ctxreduce<<<dim3(BB, 16), 256>>>();
    k_gemvV<<<DD / 8, 256>>>(Wqkv, bqkv);
    k_gemv8<<<DD / 8, 256>>>(Wo, p_oattn, bo, cls, nullptr, p_ores, DD, DD, 0,
                             0, nullptr, nullptr, nullptr);
    k_gemv8<<<FF / 8, 256>>>(W1, p_ores, b1, nullptr, nullptr, p_f, DD, FF, 1,
                             1, ln1g, ln1b, p_h1);
    k_gemv8<<<DD / 8, 256>>>(W2, p_f, b2, nullptr, p_h1, p_f2, FF, DD, 0,
                             0, nullptr, nullptr, nullptr);
    k_ln<<<BB, 256>>>(p_f2, ln2g, ln2b, outp);
}